// round 16
// baseline (speedup 1.0000x reference)
#include <cuda_runtime.h>
#include <cuda_bf16.h>
#include <cstdint>
#include <math.h>

#define B_  8
#define N_  1024
#define D_  1024
#define H_  16
#define DH_ 64
#define NEG_INF_ (-1e9f)

// Scratch (device globals — no allocation allowed)
__device__ float g_ao[B_*N_*D_];
__device__ __nv_bfloat16 g_biasB[B_*N_*N_];
__device__ __nv_bfloat16 g_hidB[8192*1024];
__device__ __nv_bfloat16 g_wB[3*1024*1024];
__device__ __nv_bfloat16 g_q[B_*N_*D_];
__device__ __nv_bfloat16 g_k[B_*N_*D_];
__device__ __nv_bfloat16 g_v[B_*N_*D_];

// ---------------------------------------------------------------------------
// Helpers
// ---------------------------------------------------------------------------
__device__ __forceinline__ uint32_t pack_bf16(float x, float y) {
    __nv_bfloat162 t = __floats2bfloat162_rn(x, y);
    return *(uint32_t*)&t;
}
__device__ __forceinline__ void mma_bf16v(float* d, const uint32_t* a, uint32_t b0, uint32_t b1) {
    asm volatile(
        "mma.sync.aligned.m16n8k16.row.col.f32.bf16.bf16.f32 "
        "{%0,%1,%2,%3}, {%4,%5,%6,%7}, {%8,%9}, {%0,%1,%2,%3};\n"
        : "+f"(d[0]), "+f"(d[1]), "+f"(d[2]), "+f"(d[3])
        : "r"(a[0]), "r"(a[1]), "r"(a[2]), "r"(a[3]), "r"(b0), "r"(b1));
}
__device__ __forceinline__ uint32_t smem_u32(const void* p) {
    return (uint32_t)__cvta_generic_to_shared(p);
}
__device__ __forceinline__ void cp16(void* dst, const void* src) {
    asm volatile("cp.async.cg.shared.global [%0], [%1], 16;\n"
                 :: "r"(smem_u32(dst)), "l"(src));
}
__device__ __forceinline__ void ldsm_x4(uint32_t* r, uint32_t addr) {
    asm volatile("ldmatrix.sync.aligned.m8n8.x4.shared.b16 {%0,%1,%2,%3}, [%4];\n"
                 : "=r"(r[0]), "=r"(r[1]), "=r"(r[2]), "=r"(r[3]) : "r"(addr));
}
__device__ __forceinline__ void ldsm_x4_t(uint32_t* r, uint32_t addr) {
    asm volatile("ldmatrix.sync.aligned.m8n8.x4.trans.shared.b16 {%0,%1,%2,%3}, [%4];\n"
                 : "=r"(r[0]), "=r"(r[1]), "=r"(r[2]), "=r"(r[3]) : "r"(addr));
}

// ---------------------------------------------------------------------------
// Kernel -1a: convert fp32 -> bf16 (4 elems/thread), hid
// ---------------------------------------------------------------------------
__global__ __launch_bounds__(256) void convert_kernel(
    const float* __restrict__ src,
    __nv_bfloat16* __restrict__ dst)
{
    long i = ((long)blockIdx.x * 256 + threadIdx.x) * 4;
    float4 v = *(const float4*)(src + i);
    uint2 o;
    o.x = pack_bf16(v.x, v.y);
    o.y = pack_bf16(v.z, v.w);
    *(uint2*)(dst + i) = o;
}

// Kernel -1b: convert all three W matrices (blockIdx.y selects)
__global__ __launch_bounds__(256) void convert_w_kernel(
    const float* __restrict__ Wq,
    const float* __restrict__ Wk,
    const float* __restrict__ Wv,
    __nv_bfloat16* __restrict__ dst)
{
    const float* src = (blockIdx.y == 0) ? Wq : (blockIdx.y == 1) ? Wk : Wv;
    long i = ((long)blockIdx.x * 256 + threadIdx.x) * 4;
    float4 v = *(const float4*)(src + i);
    uint2 o;
    o.x = pack_bf16(v.x, v.y);
    o.y = pack_bf16(v.z, v.w);
    *(uint2*)(dst + (long)blockIdx.y * D_ * D_ + i) = o;
}

// ---------------------------------------------------------------------------
// Kernel 0: bias precompute (bf16).  g_biasB = adj ? table[relpos] : -1e9
// ---------------------------------------------------------------------------
__global__ __launch_bounds__(256) void bias_kernel(
    const int* __restrict__ adj,
    const int* __restrict__ relpos,
    const float* __restrict__ rel_table)
{
    __shared__ float t[8];
    if (threadIdx.x < 6) t[threadIdx.x] = rel_table[threadIdx.x];
    __syncthreads();
    long i4 = (long)blockIdx.x * 256 + threadIdx.x;
    int4 a = *(const int4*)(adj + i4 * 4);
    int4 r = *(const int4*)(relpos + i4 * 4);
    uint2 o;
    o.x = pack_bf16(a.x ? t[r.x] : NEG_INF_, a.y ? t[r.y] : NEG_INF_);
    o.y = pack_bf16(a.z ? t[r.z] : NEG_INF_, a.w ? t[r.w] : NEG_INF_);
    *(uint2*)(g_biasB + i4 * 4) = o;
}

// ---------------------------------------------------------------------------
// Kernel 1: QKV GEMM — single-pass bf16, 3-stage cp.async + ldmatrix.
// Output plain bf16 (q pre-scaled 1/32). (unchanged R15)
// ---------------------------------------------------------------------------
#define GAP_A 40
#define GAP_B 136
#define ST_A 0
#define ST_B 5120
#define ST_TOT 9472
#define GEMM_SMEM_BYTES (3 * ST_TOT * 2)

__global__ __launch_bounds__(256, 2) void qkv_gemm_kernel(
    const __nv_bfloat16* __restrict__ hidB,
    const __nv_bfloat16* __restrict__ wBall)
{
    extern __shared__ __nv_bfloat16 sg[];

    const int z = blockIdx.z;
    const __nv_bfloat16* WB = wBall + (long)z * 1024 * 1024;
    __nv_bfloat16* C = (z == 0) ? g_q : (z == 1) ? g_k : g_v;
    const float osc = (z == 0) ? 0.03125f : 1.0f;

    const int m0 = blockIdx.y * 128;
    const int n0 = blockIdx.x * 128;
    const int tid = threadIdx.x;
    const int lane = tid & 31;
    const int warp = tid >> 5;
    const int wm = warp & 1;
    const int wn = warp >> 1;

    float acc[4][4][4];
    #pragma unroll
    for (int i = 0; i < 4; i++)
        #pragma unroll
        for (int j = 0; j < 4; j++)
            #pragma unroll
            for (int r = 0; r < 4; r++) acc[i][j][r] = 0.f;

    const int ar0 = tid >> 2, akc0 = (tid & 3) * 8;
    const int br0 = tid >> 4, bnc0 = (tid & 15) * 8;

    #define GEMM_PREFETCH(KT, BUF)                                              \
        {                                                                       \
            const int k0p = (KT) * 32;                                          \
            __nv_bfloat16* s = sg + (BUF) * ST_TOT;                             \
            _Pragma("unroll")                                                   \
            for (int u = 0; u < 2; u++) {                                       \
                int ar = ar0 + u * 64;                                          \
                cp16(s + ST_A + ar * GAP_A + akc0,                              \
                     hidB + (long)(m0 + ar) * 1024 + k0p + akc0);               \
                int br = br0 + u * 16;                                          \
                cp16(s + ST_B + br * GAP_B + bnc0,                              \
                     WB + (long)(k0p + br) * 1024 + n0 + bnc0);                 \
            }                                                                   \
            asm volatile("cp.async.commit_group;\n");                           \
        }

    GEMM_PREFETCH(0, 0)
    GEMM_PREFETCH(1, 1)

    const int a_row = (lane & 7) + ((lane >> 3) & 1) * 8;
    const int a_col8 = ((lane >> 4) & 1) * 8;
    const int b_row = (lane & 7) + ((lane >> 3) & 1) * 8;
    const int b_col8 = ((lane >> 4) & 1) * 8;

    for (int kt = 0; kt < 32; kt++) {
        if (kt < 31) {
            asm volatile("cp.async.wait_group 1;\n");
        } else {
            asm volatile("cp.async.wait_group 0;\n");
        }
        __syncthreads();

        if (kt + 2 < 32) GEMM_PREFETCH(kt + 2, (kt + 2) % 3)

        const __nv_bfloat16* s = sg + (kt % 3) * ST_TOT;
        const __nv_bfloat16* As = s + ST_A;
        const __nv_bfloat16* Bs = s + ST_B;

        #pragma unroll
        for (int ks = 0; ks < 2; ks++) {
            const int acol = ks * 16 + a_col8;
            uint32_t ahv[4][4];
            #pragma unroll
            for (int i = 0; i < 4; i++) {
                int row = wm * 64 + i * 16 + a_row;
                ldsm_x4(ahv[i], smem_u32(As + row * GAP_A + acol));
            }
            #pragma unroll
            for (int jj = 0; jj < 2; jj++) {
                int brow = ks * 16 + b_row;
                int bcol = wn * 32 + jj * 16 + b_col8;
                uint32_t bh4[4];
                ldsm_x4_t(bh4, smem_u32(Bs + brow * GAP_B + bcol));
                #pragma unroll
                for (int i = 0; i < 4; i++) {
                    mma_bf16v(acc[i][2*jj],   ahv[i], bh4[0], bh4[1]);
                    mma_bf16v(acc[i][2*jj+1], ahv[i], bh4[2], bh4[3]);
                }
            }
        }
    }

    #pragma unroll
    for (int i = 0; i < 4; i++) {
        #pragma unroll
        for (int j = 0; j < 4; j++) {
            int row = m0 + wm * 64 + i * 16 + (lane >> 2);
            int col = n0 + wn * 32 + j * 8 + (lane & 3) * 2;
            uint32_t h01 = pack_bf16(acc[i][j][0] * osc, acc[i][j][1] * osc);
            uint32_t h23 = pack_bf16(acc[i][j][2] * osc, acc[i][j][3] * osc);
            *(uint32_t*)&C[(long)row * 1024 + col] = h01;
            *(uint32_t*)&C[(long)(row + 8) * 1024 + col] = h23;
        }
    }
}

// ---------------------------------------------------------------------------
// Kernel 2: Flash attention — bf16 Q/K/V, no-max softmax, bf16 bias,
// DOUBLE-buffered K and V (2-deep group pipeline: loads for kt+2 issued at
// the end of tile kt, hidden behind the entire compute of tile kt+1).
// smem: Q + K0,K1 + V0,V1 (stride 72) = 92 KB/CTA, 2 CTAs/SM.
// ---------------------------------------------------------------------------
#define FST 72
#define TSZ (128 * FST)
#define FLASH_SMEM_BYTES (5 * TSZ * 2)

__global__ __launch_bounds__(256, 2) void flash_kernel(
    const __nv_bfloat16* __restrict__ bias)
{
    extern __shared__ __nv_bfloat16 fb[];
    __nv_bfloat16* QS = fb;
    __nv_bfloat16* KB[2] = {fb + TSZ, fb + 2 * TSZ};
    __nv_bfloat16* VB[2] = {fb + 3 * TSZ, fb + 4 * TSZ};

    const int q0 = blockIdx.x * 128;
    const int h  = blockIdx.y;
    const int b  = blockIdx.z;
    const int tid = threadIdx.x;
    const int lane = tid & 31;
    const int warp = tid >> 5;
    const int qd  = lane & 3;
    const int ln4 = lane >> 2;
    const int rowA = warp * 16 + ln4;

    const int a_row = (lane & 7) + ((lane >> 3) & 1) * 8;
    const int a_col8 = ((lane >> 4) & 1) * 8;

    #define LOAD_TILE2(DST, SRC)                                                \
        {                                                                       \
            int r_ = tid >> 1;                                                  \
            int c_ = (tid & 1) * 4;                                             \
            _Pragma("unroll")                                                   \
            for (int u_ = 0; u_ < 4; u_++)                                      \
                cp16((DST) + r_ * FST + (c_ + u_) * 8,                          \
                     (SRC) + (long)r_ * 1024 + (c_ + u_) * 8);                  \
        }

    // prologue: g0 = {Q, K0, V0}, g1 = {K1, V1}
    {
        long qoff = ((long)b * N_ + q0) * D_ + h * DH_;
        long off0 = ((long)b * N_) * D_ + h * DH_;
        LOAD_TILE2(QS, g_q + qoff)
        LOAD_TILE2(KB[0], g_k + off0)
        LOAD_TILE2(VB[0], g_v + off0)
        asm volatile("cp.async.commit_group;\n");
        long off1 = off0 + 128 * (long)D_;
        LOAD_TILE2(KB[1], g_k + off1)
        LOAD_TILE2(VB[1], g_v + off1)
        asm volatile("cp.async.commit_group;\n");
    }

    float l0 = 0.f, l1 = 0.f;
    float o[8][4];
    #pragma unroll
    for (int n = 0; n < 8; n++)
        #pragma unroll
        for (int r = 0; r < 4; r++) o[n][r] = 0.f;

    for (int kt = 0; kt < N_ / 128; kt++) {
        const int kv0 = kt * 128;
        const int bfi = kt & 1;
        asm volatile("cp.async.wait_group 1;\n");
        __syncthreads();

        // ---- S = Q K^T (plain bf16) ----
        float sc[16][4];
        #pragma unroll
        for (int j = 0; j < 16; j++)
            #pragma unroll
            for (int r = 0; r < 4; r++) sc[j][r] = 0.f;

        const __nv_bfloat16* KS = KB[bfi];
        #pragma unroll
        for (int ks = 0; ks < 4; ks++) {
            const int acol = ks * 16 + a_col8;
            uint32_t qh4[4];
            ldsm_x4(qh4, smem_u32(QS + (warp * 16 + a_row) * FST + acol));
            #pragma unroll
            for (int jb = 0; jb < 8; jb++) {
                uint32_t kh4[4];
                ldsm_x4(kh4, smem_u32(KS + (jb * 16 + a_row) * FST + acol));
                mma_bf16v(sc[2*jb],   qh4, kh4[0], kh4[2]);
                mma_bf16v(sc[2*jb+1], qh4, kh4[1], kh4[3]);
            }
        }

        // ---- P = exp(S + bias) (no-max softmax: scores bounded) ----
        {
            long base0 = ((long)b * N_ + (q0 + rowA)) * N_ + kv0;
            long base1 = base0 + 8 * (long)N_;
            #pragma unroll
            for (int j = 0; j < 16; j++) {
                int c = j * 8 + qd * 2;
                float2 b0 = __bfloat1622float2(*(const __nv_bfloat162*)(bias + base0 + c));
                float2 b1 = __bfloat1622float2(*(const __nv_bfloat162*)(bias + base1 + c));
                sc[j][0] = __expf(sc[j][0] + b0.x);
                sc[j][1] = __expf(sc[j][1] + b0.y);
                sc[j][2] = __expf(sc[j][2] + b1.x);
                sc[j][3] = __expf(sc[j][3] + b1.y);
                l0 += sc[j][0] + sc[j][1];
                l1 += sc[j][2] + sc[j][3];
            }
        }

        // ---- O += P V  (P and V plain bf16) ----
        const __nv_bfloat16* V = VB[bfi];
        #pragma unroll
        for (int kk = 0; kk < 8; kk++) {
            uint32_t ph[4];
            ph[0] = pack_bf16(sc[2*kk][0],   sc[2*kk][1]);
            ph[1] = pack_bf16(sc[2*kk][2],   sc[2*kk][3]);
            ph[2] = pack_bf16(sc[2*kk+1][0], sc[2*kk+1][1]);
            ph[3] = pack_bf16(sc[2*kk+1][2], sc[2*kk+1][3]);
            #pragma unroll
            for (int db = 0; db < 4; db++) {
                uint32_t vh4[4];
                ldsm_x4_t(vh4, smem_u32(V + (kk * 16 + a_row) * FST + db * 16 + a_col8));
                mma_bf16v(o[db*2],   ph, vh4[0], vh4[1]);
                mma_bf16v(o[db*2+1], ph, vh4[2], vh4[3]);
            }
        }

        // buffers for tile kt fully consumed — refill with tile kt+2
        __syncthreads();
        if (kt + 2 < N_ / 128) {
            long offn = ((long)b * N_ + (kt + 2) * 128) * D_ + h * DH_;
            LOAD_TILE2(KB[bfi], g_k + offn)
            LOAD_TILE2(VB[bfi], g_v + offn)
        }
        asm volatile("cp.async.commit_group;\n");   // possibly-empty group
    }

    // ---- finalize: reduce l across quad, divide, write ----
    l0 += __shfl_xor_sync(0xffffffffu, l0, 1);
    l0 += __shfl_xor_sync(0xffffffffu, l0, 2);
    l1 += __shfl_xor_sync(0xffffffffu, l1, 1);
    l1 += __shfl_xor_sync(0xffffffffu, l1, 2);
    float inv0 = 1.f / l0, inv1 = 1.f / l1;
    float* aout = g_ao + ((long)b * N_ + q0) * D_ + h * DH_;
    #pragma unroll
    for (int n = 0; n < 8; n++) {
        int col = n * 8 + qd * 2;
        float2 r0 = {o[n][0] * inv0, o[n][1] * inv0};
        float2 r1 = {o[n][2] * inv1, o[n][3] * inv1};
        *(float2*)(aout + (long)rowA * D_ + col) = r0;
        *(float2*)(aout + (long)(rowA + 8) * D_ + col) = r1;
    }
}

// ---------------------------------------------------------------------------
// Kernel 3: out = LayerNorm(relu(attn_out) + hid) * gamma + beta
// ---------------------------------------------------------------------------
__global__ __launch_bounds__(256) void epilogue_kernel(
    const float* __restrict__ hid,
    const float* __restrict__ gamma,
    const float* __restrict__ beta,
    float* __restrict__ out)
{
    __shared__ float rs[8];
    __shared__ float rq[8];
    __shared__ float stats[2];

    const long row = blockIdx.x;
    const float* a = g_ao + row * D_;
    const float* hp = hid + row * D_;
    const int c = threadIdx.x * 4;

    float4 av = *(const float4*)(a + c);
    float4 hv = *(const float4*)(hp + c);
    float4 y;
    y.x = fmaxf(av.x, 0.f) + hv.x;
    y.y = fmaxf(av.y, 0.f) + hv.y;
    y.z = fmaxf(av.z, 0.f) + hv.z;
    y.w = fmaxf(av.w, 0.f) + hv.w;

    float sum = y.x + y.y + y.z + y.w;
    float sq  = y.x * y.x + y.y * y.y + y.z * y.z + y.w * y.w;
    #pragma unroll
    for (int off = 16; off > 0; off >>= 1) {
        sum += __shfl_xor_sync(0xffffffffu, sum, off);
        sq  += __shfl_xor_sync(0xffffffffu, sq, off);
    }
    if ((threadIdx.x & 31) == 0) {
        rs[threadIdx.x >> 5] = sum;
        rq[threadIdx.x >> 5] = sq;
    }
    __syncthreads();
    if (threadIdx.x == 0) {
        float S = 0.f, Q = 0.f;
        #pragma unroll
        for (int w = 0; w < 8; w++) { S += rs[w]; Q += rq[w]; }
        float mean = S * (1.f / 1024.f);
        float var  = Q * (1.f / 1024.f) - mean * mean;
        stats[0] = mean;
        stats[1] = rsqrtf(var + 1e-5f);
    }
    __syncthreads();
    float mean = stats[0], rstd = stats[1];

    float4 g4 = *(const float4*)(gamma + c);
    float4 b4 = *(const float4*)(beta + c);
    float4 o4;
    o4.x = (y.x - mean) * rstd * g4.x + b4.x;
    o4.y = (y.y - mean) * rstd * g4.y + b4.y;
    o4.z = (y.z - mean) * rstd * g4.z + b4.z;
    o4.w = (y.w - mean) * rstd * g4.w + b4.w;
    *(float4*)(out + row * D_ + c) = o4;
}

// ---------------------------------------------------------------------------
extern "C" void kernel_launch(void* const* d_in, const int* in_sizes, int n_in,
                              void* d_out, int out_size)
{
    const float* hid      = (const float*)d_in[0];
    const int*   adj      = (const int*)d_in[1];
    const int*   relpos   = (const int*)d_in[2];
    const float* Wq       = (const float*)d_in[3];
    const float* Wk       = (const float*)d_in[4];
    const float* Wv       = (const float*)d_in[5];
    const float* rel_tab  = (const float*)d_in[6];
    const float* gamma    = (const float*)d_in[7];
    const float* beta     = (const float*)d_in[8];
    float* out = (float*)d_out;

    __nv_bfloat16 *hidB, *wB, *bias_ptr;
    cudaGetSymbolAddress((void**)&hidB, g_hidB);
    cudaGetSymbolAddress((void**)&wB, g_wB);
    cudaGetSymbolAddress((void**)&bias_ptr, g_biasB);

    convert_kernel<<<(B_ * N_ * D_) / 1024, 256>>>(hid, hidB);
    {
        dim3 wg(D_ * D_ / 1024, 3);
        convert_w_kernel<<<wg, 256>>>(Wq, Wk, Wv, wB);
    }

    bias_kernel<<<B_ * N_ * N_ / 1024, 256>>>(adj, relpos, rel_tab);

    cudaFuncSetAttribute(qkv_gemm_kernel,
                         cudaFuncAttributeMaxDynamicSharedMemorySize,
                         GEMM_SMEM_BYTES);
    dim3 ggrid(1024 / 128, 8192 / 128, 3);
    qkv_gemm_kernel<<<ggrid, 256, GEMM_SMEM_BYTES>>>(hidB, wB);

    cudaFuncSetAttribute(flash_kernel,
                         cudaFuncAttributeMaxDynamicSharedMemorySize,
                         FLASH_SMEM_BYTES);
    dim3 fgrid(N_ / 128, H_, B_);
    flash_kernel<<<fgrid, 256, FLASH_SMEM_BYTES>>>(bias_ptr);

    epilogue_kernel<<<B_ * N_, 256>>>(hid, gamma, beta, out);
}